// round 8
// baseline (speedup 1.0000x reference)
#include <cuda_runtime.h>
#include <cuda_bf16.h>
#include <math.h>

// B=32, L=1024, C=1024, E=64, TASKS=8, K=2
#define B_ 32
#define L_ 1024
#define C_ 1024
#define E_ 64
#define T_ 8
#define Y_ELEMS (B_ * L_ * C_)           // 33554432

#define CHUNKS 8                          // logit chunks per batch
#define LOGIT_BLOCKS (B_ * CHUNKS)        // 256
#define GATE_BLOCKS B_                    // 32
#define ROWS_PER_BLOCK 8
#define SCALE_BLOCKS ((B_ * L_) / ROWS_PER_BLOCK)   // 4096
#define SCALE_BASE (LOGIT_BLOCKS + GATE_BLOCKS)     // 288
#define TOTAL_BLOCKS (SCALE_BASE + SCALE_BLOCKS)    // 4384

// Scratch (__device__ globals; allocation-free rule)
__device__ float d_partial[B_ * CHUNKS * E_];  // per-chunk partial logits
__device__ float d_s[B_ * L_];                 // combined gate scale per (b,l)
__device__ float d_tm[B_ * L_];                // per-batch token-mask contrib
__device__ float d_pm[B_ * E_];                // masked probs rows
__device__ int   d_lflag[B_];                  // per-batch logit-chunk counters
__device__ int   d_flag;                       // gate-done counter
__device__ int   d_done;                       // completion counter (for reset)

__device__ __forceinline__ int ld_acquire_gpu(const int* p) {
    int v;
    asm volatile("ld.acquire.gpu.b32 %0, [%1];" : "=r"(v) : "l"(p) : "memory");
    return v;
}

__global__ __launch_bounds__(256) void fused_kernel(
        const float4* __restrict__ x,
        const float*  __restrict__ x2,
        const float*  __restrict__ G,
        const float*  __restrict__ W1,
        const float*  __restrict__ b1,
        const float*  __restrict__ W2,
        float* __restrict__ out) {
    const int tid = threadIdx.x;
    const int blk = blockIdx.x;

    if (blk < LOGIT_BLOCKS) {
        // ================= STAGE A: partial logits =================
        const int b  = blk >> 3;         // batch
        const int ch = blk & 7;          // chunk of 128 c's
        __shared__ float hg[128];
        __shared__ float part[16 * 64];  // [csub][expert]

        // hgate for c in [ch*128, ch*128+128): threads 0..127
        if (tid < 128) {
            const int c = ch * 128 + tid;
            float xr[T_];
#pragma unroll
            for (int t = 0; t < T_; t++) xr[t] = x2[b * T_ + t];
            float h = b1[c];
#pragma unroll
            for (int t = 0; t < T_; t++) h = fmaf(xr[t], W1[t * C_ + c], h);
            h = 0.5f * h * (1.0f + erff(h * 0.70710678118654752f));
            hg[tid] = h;
        }
        __syncthreads();

        // partial logits: eg = tid&15 (experts 4eg..4eg+3), csub = tid>>4 (8 c's)
        {
            const int eg   = tid & 15;
            const int csub = tid >> 4;
            const float4* W2v = (const float4*)W2;  // row = 32 float4
            float4 acc = make_float4(0.f, 0.f, 0.f, 0.f);
#pragma unroll
            for (int j = 0; j < 8; j++) {
                const int cl = csub * 8 + j;           // local c
                const int c  = ch * 128 + cl;          // global c
                const float h = hg[cl];
                const float4 w = __ldg(&W2v[c * 32 + eg]);
                acc.x = fmaf(h, w.x, acc.x);
                acc.y = fmaf(h, w.y, acc.y);
                acc.z = fmaf(h, w.z, acc.z);
                acc.w = fmaf(h, w.w, acc.w);
            }
            float* p = &part[csub * 64 + eg * 4];
            p[0] = acc.x; p[1] = acc.y; p[2] = acc.z; p[3] = acc.w;
        }
        __syncthreads();

        // reduce 16 csubs per expert; store to d_partial
        if (tid < E_) {
            float acc = 0.0f;
#pragma unroll
            for (int cs = 0; cs < 16; cs++) acc += part[cs * 64 + tid];
            d_partial[(b * CHUNKS + ch) * E_ + tid] = acc;
        }
        __syncthreads();
        if (tid == 0) {
            __threadfence();
            atomicAdd(&d_lflag[b], 1);
        }
    } else if (blk < SCALE_BASE) {
        // ================= STAGE B: per-batch gate =================
        const int b = blk - LOGIT_BLOCKS;
        __shared__ float probs_sh[E_];
        __shared__ float thresh_sh, sg1_sh, sg2_sh;
        __shared__ int   se1_sh, se2_sh;

        if (tid == 0) {
            while (ld_acquire_gpu(&d_lflag[b]) < CHUNKS) __nanosleep(32);
        }
        __syncthreads();

        if (tid < E_) {
            float acc = 0.0f;
#pragma unroll
            for (int ch = 0; ch < CHUNKS; ch++)
                acc += d_partial[(b * CHUNKS + ch) * E_ + tid];
            probs_sh[tid] = acc;   // logits
        }
        __syncthreads();

        // warp 0: softmax + top-2 via shuffles
        if (tid < 32) {
            const float la = probs_sh[tid];
            const float lb = probs_sh[tid + 32];

            float m = fmaxf(la, lb);
#pragma unroll
            for (int off = 16; off > 0; off >>= 1)
                m = fmaxf(m, __shfl_xor_sync(0xffffffffu, m, off));

            float ea = expf(la - m);
            float eb = expf(lb - m);
            float s = ea + eb;
#pragma unroll
            for (int off = 16; off > 0; off >>= 1)
                s += __shfl_xor_sync(0xffffffffu, s, off);
            const float inv = 1.0f / s;

            float pa = fmaf(ea, inv, 0.0001f);
            float pb = fmaf(eb, inv, 0.0001f);
            probs_sh[tid]      = pa;
            probs_sh[tid + 32] = pb;

            float t1, t2; int i1, i2;
            if (pa >= pb) { t1 = pa; i1 = tid;      t2 = pb; i2 = tid + 32; }
            else          { t1 = pb; i1 = tid + 32; t2 = pa; i2 = tid; }
#pragma unroll
            for (int off = 16; off > 0; off >>= 1) {
                float o1 = __shfl_xor_sync(0xffffffffu, t1, off);
                int  oi1 = __shfl_xor_sync(0xffffffffu, i1, off);
                float o2 = __shfl_xor_sync(0xffffffffu, t2, off);
                int  oi2 = __shfl_xor_sync(0xffffffffu, i2, off);
                if (o1 > t1) {
                    if (t1 > o2) { t2 = t1; i2 = i1; }
                    else         { t2 = o2; i2 = oi2; }
                    t1 = o1; i1 = oi1;
                } else if (o1 > t2) {
                    t2 = o1; i2 = oi1;
                }
            }
            if (tid == 0) {
                se1_sh = i1; se2_sh = i2;
                sg1_sh = t1; sg2_sh = t2;
                thresh_sh = t2;
            }
        }
        __syncthreads();

        if (tid < E_) {
            float p = probs_sh[tid];
            d_pm[b * E_ + tid] = (p >= thresh_sh) ? p : 0.0f;
        }

        // per-(b,l) scale + token-mask contribution; 4 l's per thread
#pragma unroll
        for (int j = 0; j < 4; j++) {
            int l = tid + j * 256;
            float ga = G[((size_t)(b * E_ + se1_sh)) * L_ + l];
            float gb = G[((size_t)(b * E_ + se2_sh)) * L_ + l];
            d_s[b * L_ + l]  = fmaf(sg1_sh, ga, sg2_sh * gb);
            d_tm[b * L_ + l] = ga + gb;
        }

        __threadfence();
        __syncthreads();
        if (tid == 0) atomicAdd(&d_flag, 1);
    } else {
        // ===================== SCALE (8 rows/block) =====================
        const int idx  = blk - SCALE_BASE;
        const int row0 = idx * ROWS_PER_BLOCK;
        const size_t base = (size_t)row0 * 256 + tid;

        // Issue all 8 streaming loads (32 KB in flight per block).
        float4 v[ROWS_PER_BLOCK];
#pragma unroll
        for (int r = 0; r < ROWS_PER_BLOCK; r++)
            v[r] = __ldcs(&x[base + (size_t)r * 256]);

        // Short wait for gate data readiness.
        if (tid == 0) {
            while (ld_acquire_gpu(&d_flag) < GATE_BLOCKS) __nanosleep(64);
        }
        __syncthreads();

        float4* y = (float4*)out;
#pragma unroll
        for (int r = 0; r < ROWS_PER_BLOCK; r++) {
            const float s = d_s[row0 + r];
            float4 w = v[r];
            w.x *= s; w.y *= s; w.z *= s; w.w *= s;
            __stcs(&y[base + (size_t)r * 256], w);
        }

        // First scale block: masks.
        // Layout: [y (32M), expert_mask (64), token_mask (1024)]
        if (idx == 0) {
#pragma unroll
            for (int j = 0; j < 4; j++) {
                int l = tid + j * 256;
                float tm = 0.0f;
#pragma unroll
                for (int b = 0; b < B_; b++) tm += d_tm[b * L_ + l];
                out[Y_ELEMS + E_ + l] = tm;
            }
            if (tid < E_) {
                float em = 0.0f;
#pragma unroll
                for (int b = 0; b < B_; b++) em += d_pm[b * E_ + tid];
                out[Y_ELEMS + tid] = em;
            }
        }
    }

    // -------- reset handshake state for next graph replay --------
    __syncthreads();
    if (tid == 0) {
        int old = atomicAdd(&d_done, 1);
        if (old == TOTAL_BLOCKS - 1) {
#pragma unroll
            for (int b = 0; b < B_; b++) d_lflag[b] = 0;
            d_flag = 0;
            d_done = 0;
        }
    }
}

extern "C" void kernel_launch(void* const* d_in, const int* in_sizes, int n_in,
                              void* d_out, int out_size) {
    const float* x  = (const float*)d_in[0];  // input_features (32,1024,1024)
    const float* x2 = (const float*)d_in[1];  // input_features2 (32,8)
    const float* G  = (const float*)d_in[2];  // G (32,64,1024)
    const float* W1 = (const float*)d_in[3];  // W1 (8,1024)
    const float* b1 = (const float*)d_in[4];  // b1 (1024,)
    const float* W2 = (const float*)d_in[5];  // W2 (1024,128)
    float* out = (float*)d_out;

    fused_kernel<<<TOTAL_BLOCKS, 256>>>((const float4*)x, x2, G, W1, b1, W2, out);
}